// round 8
// baseline (speedup 1.0000x reference)
#include <cuda_runtime.h>
#include <cuda_fp16.h>
#include <cstdint>

// out = x @ W^T (GAT attention cancels: softmax rows sum to 1; final einsum
// multiplies h by sum_j alpha = 1; adj/a_w dead).  M=8192, N=256, K=256, NT.
//
// R7 lesson: converting x in a pre-pass cost 5.8us. Fuse it: GEMM consumes x
// fp32 via register-staged LDG+cvt+STS double buffer; W pre-converted to fp16
// (tiny, L2-resident); all of B per CTA loaded in ONE cp.async group.

#define THREADS 256
#define BM 64
#define BN 128
#define KGLOB 256
#define NCHUNK 4
#define A_STAGE_B 8192          // 64 rows x 128B (64 fp16)
#define B_TILE_B 16384          // 128 rows x 128B per k-chunk
#define SB_BYTES (4 * B_TILE_B) // 64KB: full B slice 128x256 fp16
#define SMEM_TOTAL (SB_BYTES + 2 * A_STAGE_B)   // 80KB

__device__ __align__(16) __half g_wh[256 * 256];

__device__ __forceinline__ uint32_t smem_u32(const void* p) {
    uint32_t a;
    asm("{ .reg .u64 t; cvta.to.shared.u64 t, %1; cvt.u32.u64 %0, t; }" : "=r"(a) : "l"(p));
    return a;
}
__device__ __forceinline__ uint32_t swz(uint32_t off) { return off ^ ((off >> 3) & 0x70); }

__device__ __forceinline__ void cp16(uint32_t dst, const void* src) {
    asm volatile("cp.async.cg.shared.global [%0], [%1], 16;" :: "r"(dst), "l"(src) : "memory");
}
__device__ __forceinline__ void cp_commit() {
    asm volatile("cp.async.commit_group;" ::: "memory");
}
__device__ __forceinline__ void cp_wait0() {
    asm volatile("cp.async.wait_group 0;" ::: "memory");
}

__device__ __forceinline__ void ldsm4(uint32_t& r0, uint32_t& r1, uint32_t& r2, uint32_t& r3,
                                      uint32_t addr) {
    asm volatile("ldmatrix.sync.aligned.m8n8.x4.shared.b16 {%0,%1,%2,%3}, [%4];"
                 : "=r"(r0), "=r"(r1), "=r"(r2), "=r"(r3) : "r"(addr));
}
__device__ __forceinline__ void mma16816(float* c, const uint32_t* a, const uint32_t* b) {
    asm volatile("mma.sync.aligned.m16n8k16.row.col.f32.f16.f16.f32 "
                 "{%0,%1,%2,%3}, {%4,%5,%6,%7}, {%8,%9}, {%0,%1,%2,%3};"
                 : "+f"(c[0]), "+f"(c[1]), "+f"(c[2]), "+f"(c[3])
                 : "r"(a[0]), "r"(a[1]), "r"(a[2]), "r"(a[3]), "r"(b[0]), "r"(b[1]));
}
__device__ __forceinline__ uint32_t pack2(float x, float y) {
    __half2 h = __floats2half2_rn(x, y);
    return *reinterpret_cast<uint32_t*>(&h);
}

// ---------------- convert W: fp32 -> fp16 (tiny) ----------------
__global__ void __launch_bounds__(256)
cvt_w(const float4* __restrict__ in)
{
    uint4* out = (uint4*)g_wh;
    int i = blockIdx.x * 256 + threadIdx.x;   // 8192 uint4 outputs
    float4 v0 = in[2 * i];
    float4 v1 = in[2 * i + 1];
    uint4 p;
    p.x = pack2(v0.x, v0.y); p.y = pack2(v0.z, v0.w);
    p.z = pack2(v1.x, v1.y); p.w = pack2(v1.z, v1.w);
    out[i] = p;
}

// ---------------- fused GEMM ----------------
__global__ void __launch_bounds__(THREADS)
gat_gemm3(const float* __restrict__ A, float* __restrict__ C)
{
    extern __shared__ __align__(1024) uint8_t smem[];
    uint8_t* sB = smem;                    // 64KB, 4 chunk tiles of 16KB
    uint8_t* sA = smem + SB_BYTES;         // 2 stages of 8KB

    const int tid = threadIdx.x;
    const int wid = tid >> 5;
    const int lid = tid & 31;
    const int bm = blockIdx.y, bn = blockIdx.x;
    const int wm = wid & 1;          // 2 warp rows of 32
    const int wn = wid >> 1;         // 4 warp cols of 32

    const float* Ag = A + (size_t)(bm * BM) * KGLOB;
    const __half* Bg = g_wh + (size_t)(bn * BN) * KGLOB;

    // ---- B: one-shot cp.async of the full 128x256 fp16 slice ----
    {
        const int r8 = tid >> 3;          // 0..31
        const int sl = tid & 7;           // 16B slot in 128B row
#pragma unroll
        for (int c = 0; c < NCHUNK; c++) {
            uint8_t* tB = sB + c * B_TILE_B;
#pragma unroll
            for (int i = 0; i < 4; i++) {
                int r = r8 + i * 32;      // 0..127
                cp16(smem_u32(tB + swz((uint32_t)(r * 128 + sl * 16))),
                     Bg + (size_t)r * KGLOB + c * 64 + sl * 8);
            }
        }
        cp_commit();
    }

    // ---- A register staging: chunk = 64 rows x 64 k fp32, 4 float4/thread ----
    const int ar = tid >> 2;              // row 0..63
    const int as = tid & 3;               // slot base
    float4 ra[4];

    auto lda = [&](int c) {
        const float* Ac = Ag + c * 64;
#pragma unroll
        for (int i = 0; i < 4; i++)
            ra[i] = *(const float4*)(Ac + (size_t)ar * KGLOB + (as + i * 4) * 4);
    };
    auto sta = [&](int s) {
        uint8_t* tA = sA + s * A_STAGE_B;
#pragma unroll
        for (int i = 0; i < 4; i++) {
            uint2 p;
            p.x = pack2(ra[i].x, ra[i].y);
            p.y = pack2(ra[i].z, ra[i].w);
            *(uint2*)(tA + swz((uint32_t)(ar * 128 + (as + i * 4) * 8))) = p;
        }
    };

    lda(0);
    sta(0);
    lda(1);
    cp_wait0();
    __syncthreads();        // B fully resident, A stage0 visible

    float acc[2][4][4];
#pragma unroll
    for (int i = 0; i < 2; i++)
#pragma unroll
        for (int j = 0; j < 4; j++)
#pragma unroll
            for (int k = 0; k < 4; k++) acc[i][j][k] = 0.f;

    const uint32_t a_row = (lid & 15);
    const uint32_t a_cb  = (lid >> 4) * 16;
    const uint32_t b_row = (lid & 7) + ((lid >> 4) << 3);
    const uint32_t b_cb  = ((lid >> 3) & 1) * 16;
    const uint32_t sAb = smem_u32(sA);
    const uint32_t sBb = smem_u32(sB);

#pragma unroll
    for (int c = 0; c < NCHUNK; c++) {
        if (c + 1 < NCHUNK) sta((c + 1) & 1);     // stage freed by prior sync
        if (c + 2 < NCHUNK) lda(c + 2);           // latency hidden by 2 MMA phases

        const uint32_t stA = (uint32_t)(c & 1) * A_STAGE_B;
        const uint32_t stB = (uint32_t)c * B_TILE_B;
#pragma unroll
        for (int ks = 0; ks < 4; ks++) {
            const uint32_t kb = (uint32_t)ks * 32;
            uint32_t af[4];
            // A rows: wm*32 + {0,16} via x4 ldmatrix over 16 rows each
            uint32_t a0[4], a1[4];
            ldsm4(a0[0], a0[1], a0[2], a0[3],
                  sAb + stA + swz((wm * 32 + 0 + a_row) * 128 + kb + a_cb));
            ldsm4(a1[0], a1[1], a1[2], a1[3],
                  sAb + stA + swz((wm * 32 + 16 + a_row) * 128 + kb + a_cb));
            uint32_t b[4][2];
#pragma unroll
            for (int ntp = 0; ntp < 2; ntp++)
                ldsm4(b[2 * ntp][0], b[2 * ntp][1], b[2 * ntp + 1][0], b[2 * ntp + 1][1],
                      sBb + stB + swz((wn * 32 + ntp * 16 + b_row) * 128 + kb + b_cb));
#pragma unroll
            for (int nt = 0; nt < 4; nt++) {
                mma16816(acc[0][nt], a0, b[nt]);
                mma16816(acc[1][nt], a1, b[nt]);
            }
            (void)af;
        }
        if (c + 1 < NCHUNK) __syncthreads();
    }

    // ---- epilogue: fp32 float2 stores ----
    const int g = lid >> 2, tig = lid & 3;
#pragma unroll
    for (int mt = 0; mt < 2; mt++) {
#pragma unroll
        for (int nt = 0; nt < 4; nt++) {
            int row = bm * BM + wm * 32 + mt * 16 + g;
            int col = bn * BN + wn * 32 + nt * 8 + 2 * tig;
            *(float2*)(C + (size_t)row * 256 + col) = make_float2(acc[mt][nt][0], acc[mt][nt][1]);
            *(float2*)(C + (size_t)(row + 8) * 256 + col) = make_float2(acc[mt][nt][2], acc[mt][nt][3]);
        }
    }
}

extern "C" void kernel_launch(void* const* d_in, const int* in_sizes, int n_in,
                              void* d_out, int out_size)
{
    const float* x = (const float*)d_in[0];
    const float* W = (const float*)d_in[2];
    float* out = (float*)d_out;

    // W: 65536 elems = 32768 float4 in, 8192 uint4 out
    cvt_w<<<32, 256>>>((const float4*)W);

    cudaFuncSetAttribute(gat_gemm3, cudaFuncAttributeMaxDynamicSharedMemorySize, SMEM_TOTAL);
    dim3 grid(256 / BN, 8192 / BM);   // (2, 128) = 256 CTAs
    gat_gemm3<<<grid, THREADS, SMEM_TOTAL>>>(x, out);
}